// round 1
// baseline (speedup 1.0000x reference)
#include <cuda_runtime.h>
#include <cuda_bf16.h>

// Problem constants: B=4, H=16, S=1024, D=64
#define SQ 1024
#define DD 64
#define QT 32           // q rows per CTA
#define NBH 64          // B*H
#define SS_STRIDE 1028  // sS row stride (pad: 1028 % 32 banks = 4 -> de-conflicts row reads)
#define KV_STRIDE 68    // K/V tile row stride (16B-aligned, padded)
#define Q_STRIDE 68

__global__ __launch_bounds__(256, 1)
void attn_fused_kernel(const float* __restrict__ Q,
                       const float* __restrict__ K,
                       const float* __restrict__ V,
                       const float* __restrict__ bias,
                       float* __restrict__ out)
{
    extern __shared__ float smem[];
    float* sS  = smem;                       // [QT][SS_STRIDE]  scores -> probs
    float* sQ  = sS + QT * SS_STRIDE;        // [QT][Q_STRIDE]
    float* sKV = sQ + QT * Q_STRIDE;         // [64][KV_STRIDE]  (K transposed / V natural)

    const int t  = threadIdx.x;
    const int tx = t & 15;                   // 16 column-groups (4 cols each)
    const int ty = t >> 4;                   // 16 row slots (each thread: rows ty, ty+16)
    const int qtile = blockIdx.x;
    const int bh    = blockIdx.y;
    const int q0    = qtile * QT;

    const float* Qb = Q + ((size_t)bh * SQ + q0) * DD;
    const float* Kb = K + (size_t)bh * SQ * DD;
    const float* Vb = V + (size_t)bh * SQ * DD;
    float* outO = out + ((size_t)bh * SQ + q0) * DD;
    float* outA = out + (size_t)NBH * SQ * DD + ((size_t)bh * SQ + q0) * SQ;

    // ---- load Q tile (32 x 64) into smem ----
    for (int i = t; i < QT * 16; i += 256) {
        int r = i >> 4, c = i & 15;
        float4 v = ((const float4*)Qb)[r * 16 + c];
        *(float4*)&sQ[r * Q_STRIDE + c * 4] = v;
    }

    const float scale = 0.125f;  // 1/sqrt(64)

    // ---- phase 1: scores = Q K^T * scale + bias, into sS ----
    for (int kt = 0; kt < 16; kt++) {
        __syncthreads();
        // load 64-key K tile TRANSPOSED: sKV[d][kcol]
        for (int i = t; i < 64 * 16; i += 256) {
            int kr = i >> 4, c = i & 15;
            float4 v = ((const float4*)(Kb + (size_t)(kt * 64 + kr) * DD))[c];
            sKV[(c * 4 + 0) * KV_STRIDE + kr] = v.x;
            sKV[(c * 4 + 1) * KV_STRIDE + kr] = v.y;
            sKV[(c * 4 + 2) * KV_STRIDE + kr] = v.z;
            sKV[(c * 4 + 3) * KV_STRIDE + kr] = v.w;
        }
        __syncthreads();

        float4 a0 = make_float4(0.f, 0.f, 0.f, 0.f);
        float4 a1 = make_float4(0.f, 0.f, 0.f, 0.f);
        #pragma unroll 16
        for (int d = 0; d < 64; d++) {
            float q0v = sQ[ty * Q_STRIDE + d];
            float q1v = sQ[(ty + 16) * Q_STRIDE + d];
            float4 kk = *(float4*)&sKV[d * KV_STRIDE + tx * 4];
            a0.x += q0v * kk.x; a0.y += q0v * kk.y; a0.z += q0v * kk.z; a0.w += q0v * kk.w;
            a1.x += q1v * kk.x; a1.y += q1v * kk.y; a1.z += q1v * kk.z; a1.w += q1v * kk.w;
        }
        int kg = kt * 64 + tx * 4;
        float4 b0 = *(const float4*)&bias[(size_t)(q0 + ty) * SQ + kg];
        float4 b1 = *(const float4*)&bias[(size_t)(q0 + ty + 16) * SQ + kg];
        float4 s0, s1;
        s0.x = a0.x * scale + b0.x; s0.y = a0.y * scale + b0.y;
        s0.z = a0.z * scale + b0.z; s0.w = a0.w * scale + b0.w;
        s1.x = a1.x * scale + b1.x; s1.y = a1.y * scale + b1.y;
        s1.z = a1.z * scale + b1.z; s1.w = a1.w * scale + b1.w;
        *(float4*)&sS[ty * SS_STRIDE + kg]        = s0;
        *(float4*)&sS[(ty + 16) * SS_STRIDE + kg] = s1;
    }
    __syncthreads();

    // ---- phase 2: row softmax in sS; write normalized P to gmem ----
    {
        const int w = t >> 5, lane = t & 31;
        for (int r = w; r < QT; r += 8) {
            float4* row = (float4*)&sS[r * SS_STRIDE];
            float m = -1e30f;
            #pragma unroll
            for (int i = 0; i < 8; i++) {
                float4 v = row[lane + i * 32];
                m = fmaxf(m, fmaxf(fmaxf(v.x, v.y), fmaxf(v.z, v.w)));
            }
            #pragma unroll
            for (int off = 16; off > 0; off >>= 1)
                m = fmaxf(m, __shfl_xor_sync(0xffffffffu, m, off));
            float s = 0.f;
            #pragma unroll
            for (int i = 0; i < 8; i++) {
                float4 v = row[lane + i * 32];
                v.x = __expf(v.x - m); v.y = __expf(v.y - m);
                v.z = __expf(v.z - m); v.w = __expf(v.w - m);
                s += v.x + v.y + v.z + v.w;
                row[lane + i * 32] = v;
            }
            #pragma unroll
            for (int off = 16; off > 0; off >>= 1)
                s += __shfl_xor_sync(0xffffffffu, s, off);
            float inv = 1.0f / s;
            float4* arow = (float4*)&outA[(size_t)r * SQ];
            #pragma unroll
            for (int i = 0; i < 8; i++) {
                float4 v = row[lane + i * 32];
                v.x *= inv; v.y *= inv; v.z *= inv; v.w *= inv;
                row[lane + i * 32] = v;   // keep normalized P for PV
                arow[lane + i * 32] = v;  // coalesced 16B store to gmem
            }
        }
    }

    // ---- phase 3: output = P V ----
    float4 o0 = make_float4(0.f, 0.f, 0.f, 0.f);
    float4 o1 = make_float4(0.f, 0.f, 0.f, 0.f);
    for (int kt = 0; kt < 16; kt++) {
        __syncthreads();   // protect sKV reuse
        for (int i = t; i < 64 * 16; i += 256) {
            int kr = i >> 4, c = i & 15;
            float4 v = ((const float4*)(Vb + (size_t)(kt * 64 + kr) * DD))[c];
            *(float4*)&sKV[kr * KV_STRIDE + c * 4] = v;
        }
        __syncthreads();
        #pragma unroll 16
        for (int k = 0; k < 64; k++) {
            float p0 = sS[ty * SS_STRIDE + kt * 64 + k];
            float p1 = sS[(ty + 16) * SS_STRIDE + kt * 64 + k];
            float4 vv = *(float4*)&sKV[k * KV_STRIDE + tx * 4];
            o0.x += p0 * vv.x; o0.y += p0 * vv.y; o0.z += p0 * vv.z; o0.w += p0 * vv.w;
            o1.x += p1 * vv.x; o1.y += p1 * vv.y; o1.z += p1 * vv.z; o1.w += p1 * vv.w;
        }
    }
    *(float4*)&outO[ty * DD + tx * 4]        = o0;
    *(float4*)&outO[(ty + 16) * DD + tx * 4] = o1;
}

extern "C" void kernel_launch(void* const* d_in, const int* in_sizes, int n_in,
                              void* d_out, int out_size)
{
    const float* Q    = (const float*)d_in[0];
    const float* K    = (const float*)d_in[1];
    const float* V    = (const float*)d_in[2];
    const float* bias = (const float*)d_in[3];
    float* out        = (float*)d_out;

    const size_t smem_bytes =
        (size_t)(QT * SS_STRIDE + QT * Q_STRIDE + 64 * KV_STRIDE) * sizeof(float);
    cudaFuncSetAttribute(attn_fused_kernel,
                         cudaFuncAttributeMaxDynamicSharedMemorySize,
                         (int)smem_bytes);

    dim3 grid(SQ / QT, NBH);
    attn_fused_kernel<<<grid, 256, smem_bytes>>>(Q, K, V, bias, out);
}

// round 2
// speedup vs baseline: 1.6324x; 1.6324x over previous
#include <cuda_runtime.h>
#include <cuda_bf16.h>
#include <cstdint>

// B=4, H=16, S=1024, D=64 ; out = [O (64*1024*64 f32)] ++ [attn (64*1024*1024 f32)]
#define SQ   1024
#define DD   64
#define QT   32
#define NBH  64
#define QS   68   // sQ / sP / sK row stride (floats)
#define VS   72   // sV row stride (floats) — conflict-free for row=lane%4 pattern

__device__ __forceinline__ uint32_t f2tf32(float x) {
    uint32_t r;
    asm("cvt.rna.tf32.f32 %0, %1;" : "=r"(r) : "f"(x));
    return r;
}

__device__ __forceinline__ void mma_tf32(float c[4],
                                         uint32_t a0, uint32_t a1, uint32_t a2, uint32_t a3,
                                         uint32_t b0, uint32_t b1) {
    asm volatile(
        "mma.sync.aligned.m16n8k8.row.col.f32.tf32.tf32.f32 "
        "{%0,%1,%2,%3}, {%4,%5,%6,%7}, {%8,%9}, {%0,%1,%2,%3};\n"
        : "+f"(c[0]), "+f"(c[1]), "+f"(c[2]), "+f"(c[3])
        : "r"(a0), "r"(a1), "r"(a2), "r"(a3), "r"(b0), "r"(b1));
}

__global__ __launch_bounds__(256, 1)
void attn_mma_kernel(const float* __restrict__ Q,
                     const float* __restrict__ K,
                     const float* __restrict__ V,
                     const float* __restrict__ bias,
                     float* __restrict__ out)
{
    __shared__ float sQhi[QT * QS];
    __shared__ float sQlo[QT * QS];
    __shared__ float sKV[64 * VS];     // K chunks (stride QS) / V chunks (stride VS)
    __shared__ float sP[QT * QS];
    __shared__ float sRed[QT * 4];

    const int t    = threadIdx.x;
    const int lane = t & 31;
    const int w    = t >> 5;
    const int qh   = w >> 2;          // q half (0/1): rows qh*16 .. +15
    const int cg   = w & 3;           // column group: owns n-tiles nt%4==cg
    const int gid  = lane >> 2;       // mma groupID (0..7)
    const int tig  = lane & 3;        // mma thread-in-group (0..3)

    const int bh = blockIdx.y;
    const int q0 = blockIdx.x * QT;

    const float* Qb = Q + ((size_t)bh * SQ + q0) * DD;
    const float* Kb = K + (size_t)bh * SQ * DD;
    const float* Vb = V + (size_t)bh * SQ * DD;
    float* outO = out + ((size_t)bh * SQ + q0) * DD;
    float* outA = out + (size_t)NBH * SQ * DD + ((size_t)bh * SQ + q0) * SQ;

    // ---- stage Q tile split hi/lo ----
    for (int i = t; i < QT * 16; i += 256) {
        int r = i >> 4, c = i & 15;
        float4 q = ((const float4*)Qb)[r * 16 + c];
        uint32_t hx = f2tf32(q.x), hy = f2tf32(q.y), hz = f2tf32(q.z), hw = f2tf32(q.w);
        float4 hi = make_float4(__uint_as_float(hx), __uint_as_float(hy),
                                __uint_as_float(hz), __uint_as_float(hw));
        float4 lo = make_float4(q.x - hi.x, q.y - hi.y, q.z - hi.z, q.w - hi.w);
        *(float4*)&sQhi[r * QS + c * 4] = hi;
        *(float4*)&sQlo[r * QS + c * 4] = lo;
    }

    float acc[32][4];
    #pragma unroll
    for (int j = 0; j < 32; j++) {
        acc[j][0] = 0.f; acc[j][1] = 0.f; acc[j][2] = 0.f; acc[j][3] = 0.f;
    }

    const int rowA = qh * 16 + gid;   // local q row for fragment slot 0/1

    // ================= phase 1: scores = Q K^T (3xTF32) =================
    #pragma unroll
    for (int kt = 0; kt < 16; kt++) {
        __syncthreads();
        for (int i = t; i < 64 * 16; i += 256) {
            int r = i >> 4, c = i & 15;
            float4 v = ((const float4*)Kb)[(kt * 64 + r) * 16 + c];
            *(float4*)&sKV[r * QS + c * 4] = v;
        }
        __syncthreads();

        #pragma unroll
        for (int ds = 0; ds < 8; ds++) {
            const int d0 = ds * 8;
            uint32_t aH0 = __float_as_uint(sQhi[rowA * QS + d0 + tig]);
            uint32_t aH1 = __float_as_uint(sQhi[(rowA + 8) * QS + d0 + tig]);
            uint32_t aH2 = __float_as_uint(sQhi[rowA * QS + d0 + tig + 4]);
            uint32_t aH3 = __float_as_uint(sQhi[(rowA + 8) * QS + d0 + tig + 4]);
            uint32_t aL0 = __float_as_uint(sQlo[rowA * QS + d0 + tig]);
            uint32_t aL1 = __float_as_uint(sQlo[(rowA + 8) * QS + d0 + tig]);
            uint32_t aL2 = __float_as_uint(sQlo[rowA * QS + d0 + tig + 4]);
            uint32_t aL3 = __float_as_uint(sQlo[(rowA + 8) * QS + d0 + tig + 4]);

            #pragma unroll
            for (int e = 0; e < 2; e++) {
                const int kb = (cg + 4 * e) * 8;          // local key base
                float k0 = sKV[(kb + gid) * QS + d0 + tig];
                float k1 = sKV[(kb + gid) * QS + d0 + tig + 4];
                uint32_t b0h = f2tf32(k0), b1h = f2tf32(k1);
                uint32_t b0l = __float_as_uint(k0 - __uint_as_float(b0h));
                uint32_t b1l = __float_as_uint(k1 - __uint_as_float(b1h));
                float* c = acc[2 * kt + e];
                mma_tf32(c, aH0, aH1, aH2, aH3, b0h, b1h);
                mma_tf32(c, aH0, aH1, aH2, aH3, b0l, b1l);
                mma_tf32(c, aL0, aL1, aL2, aL3, b0h, b1h);
            }
        }
    }

    // ================= phase 2: scale + bias + softmax (in regs) =================
    const float scale = 0.125f;
    float m1 = -1e30f, m2 = -1e30f;
    #pragma unroll
    for (int j = 0; j < 32; j++) {
        const int nt  = (j >> 1) * 8 + cg + (j & 1) * 4;
        const int col = nt * 8 + 2 * tig;
        float2 b1v = *(const float2*)&bias[(size_t)(q0 + rowA) * SQ + col];
        float2 b2v = *(const float2*)&bias[(size_t)(q0 + rowA + 8) * SQ + col];
        acc[j][0] = acc[j][0] * scale + b1v.x;
        acc[j][1] = acc[j][1] * scale + b1v.y;
        acc[j][2] = acc[j][2] * scale + b2v.x;
        acc[j][3] = acc[j][3] * scale + b2v.y;
        m1 = fmaxf(m1, fmaxf(acc[j][0], acc[j][1]));
        m2 = fmaxf(m2, fmaxf(acc[j][2], acc[j][3]));
    }
    m1 = fmaxf(m1, __shfl_xor_sync(0xffffffffu, m1, 1));
    m1 = fmaxf(m1, __shfl_xor_sync(0xffffffffu, m1, 2));
    m2 = fmaxf(m2, __shfl_xor_sync(0xffffffffu, m2, 1));
    m2 = fmaxf(m2, __shfl_xor_sync(0xffffffffu, m2, 2));
    if (tig == 0) {
        sRed[rowA * 4 + cg]       = m1;
        sRed[(rowA + 8) * 4 + cg] = m2;
    }
    __syncthreads();
    m1 = fmaxf(fmaxf(sRed[rowA * 4 + 0], sRed[rowA * 4 + 1]),
               fmaxf(sRed[rowA * 4 + 2], sRed[rowA * 4 + 3]));
    m2 = fmaxf(fmaxf(sRed[(rowA + 8) * 4 + 0], sRed[(rowA + 8) * 4 + 1]),
               fmaxf(sRed[(rowA + 8) * 4 + 2], sRed[(rowA + 8) * 4 + 3]));

    float s1 = 0.f, s2 = 0.f;
    #pragma unroll
    for (int j = 0; j < 32; j++) {
        acc[j][0] = __expf(acc[j][0] - m1);
        acc[j][1] = __expf(acc[j][1] - m1);
        acc[j][2] = __expf(acc[j][2] - m2);
        acc[j][3] = __expf(acc[j][3] - m2);
        s1 += acc[j][0] + acc[j][1];
        s2 += acc[j][2] + acc[j][3];
    }
    s1 += __shfl_xor_sync(0xffffffffu, s1, 1);
    s1 += __shfl_xor_sync(0xffffffffu, s1, 2);
    s2 += __shfl_xor_sync(0xffffffffu, s2, 1);
    s2 += __shfl_xor_sync(0xffffffffu, s2, 2);
    __syncthreads();   // max reads done before overwriting sRed
    if (tig == 0) {
        sRed[rowA * 4 + cg]       = s1;
        sRed[(rowA + 8) * 4 + cg] = s2;
    }
    __syncthreads();
    float inv1 = 1.0f / (sRed[rowA * 4 + 0] + sRed[rowA * 4 + 1] +
                         sRed[rowA * 4 + 2] + sRed[rowA * 4 + 3]);
    float inv2 = 1.0f / (sRed[(rowA + 8) * 4 + 0] + sRed[(rowA + 8) * 4 + 1] +
                         sRed[(rowA + 8) * 4 + 2] + sRed[(rowA + 8) * 4 + 3]);
    #pragma unroll
    for (int j = 0; j < 32; j++) {
        acc[j][0] *= inv1; acc[j][1] *= inv1;
        acc[j][2] *= inv2; acc[j][3] *= inv2;
    }

    // ================= phase 3: out = P V  (3xTF32), stage P per chunk =================
    float o[2][4];
    #pragma unroll
    for (int e = 0; e < 2; e++) {
        o[e][0] = 0.f; o[e][1] = 0.f; o[e][2] = 0.f; o[e][3] = 0.f;
    }

    #pragma unroll
    for (int kt = 0; kt < 16; kt++) {
        __syncthreads();
        // stage this warp's P columns of chunk kt into sP (32 x 64, stride QS)
        #pragma unroll
        for (int e = 0; e < 2; e++) {
            const int lt = (cg + 4 * e) * 8;
            const int j  = 2 * kt + e;
            *(float2*)&sP[rowA * QS + lt + 2 * tig]       = make_float2(acc[j][0], acc[j][1]);
            *(float2*)&sP[(rowA + 8) * QS + lt + 2 * tig] = make_float2(acc[j][2], acc[j][3]);
        }
        // fill V chunk (64 x 64, stride VS)
        for (int i = t; i < 64 * 16; i += 256) {
            int r = i >> 4, c = i & 15;
            float4 v = ((const float4*)Vb)[(kt * 64 + r) * 16 + c];
            *(float4*)&sKV[r * VS + c * 4] = v;
        }
        __syncthreads();

        // coalesced attn write for this chunk
        #pragma unroll
        for (int i = 0; i < 2; i++) {
            int idx = i * 256 + t;              // 0..511 float4s
            int r = idx >> 4, c4 = idx & 15;
            float4 p = *(float4*)&sP[r * QS + c4 * 4];
            *(float4*)&outA[(size_t)r * SQ + kt * 64 + c4 * 4] = p;
        }

        #pragma unroll
        for (int ks = 0; ks < 8; ks++) {
            const int k0 = ks * 8;
            float p0 = sP[rowA * QS + k0 + tig];
            float p1 = sP[(rowA + 8) * QS + k0 + tig];
            float p2 = sP[rowA * QS + k0 + tig + 4];
            float p3 = sP[(rowA + 8) * QS + k0 + tig + 4];
            uint32_t aH0 = f2tf32(p0), aH1 = f2tf32(p1), aH2 = f2tf32(p2), aH3 = f2tf32(p3);
            uint32_t aL0 = __float_as_uint(p0 - __uint_as_float(aH0));
            uint32_t aL1 = __float_as_uint(p1 - __uint_as_float(aH1));
            uint32_t aL2 = __float_as_uint(p2 - __uint_as_float(aH2));
            uint32_t aL3 = __float_as_uint(p3 - __uint_as_float(aH3));

            #pragma unroll
            for (int e = 0; e < 2; e++) {
                const int db = (cg * 2 + e) * 8;
                float v0 = sKV[(k0 + tig) * VS + db + gid];
                float v1 = sKV[(k0 + tig + 4) * VS + db + gid];
                uint32_t b0h = f2tf32(v0), b1h = f2tf32(v1);
                uint32_t b0l = __float_as_uint(v0 - __uint_as_float(b0h));
                uint32_t b1l = __float_as_uint(v1 - __uint_as_float(b1h));
                mma_tf32(o[e], aH0, aH1, aH2, aH3, b0h, b1h);
                mma_tf32(o[e], aH0, aH1, aH2, aH3, b0l, b1l);
                mma_tf32(o[e], aL0, aL1, aL2, aL3, b0h, b1h);
            }
        }
    }

    // ---- write O ----
    #pragma unroll
    for (int e = 0; e < 2; e++) {
        const int db = cg * 16 + e * 8 + 2 * tig;
        *(float2*)&outO[(size_t)rowA * DD + db]       = make_float2(o[e][0], o[e][1]);
        *(float2*)&outO[(size_t)(rowA + 8) * DD + db] = make_float2(o[e][2], o[e][3]);
    }
}

extern "C" void kernel_launch(void* const* d_in, const int* in_sizes, int n_in,
                              void* d_out, int out_size)
{
    const float* Q    = (const float*)d_in[0];
    const float* K    = (const float*)d_in[1];
    const float* V    = (const float*)d_in[2];
    const float* bias = (const float*)d_in[3];
    float* out        = (float*)d_out;

    dim3 grid(SQ / QT, NBH);
    attn_mma_kernel<<<grid, 256>>>(Q, K, V, bias, out);
}

// round 4
// speedup vs baseline: 3.4925x; 2.1394x over previous
#include <cuda_runtime.h>
#include <cstdint>

// B=4, H=16, S=1024, D=64 ; out = [O (64*1024*64 f32)] ++ [attn (64*1024*1024 f32)]
#define SQ   1024
#define DD   64
#define QT   32
#define NBH  64
#define QS   68       // sQhi / sQlo / sP row stride
#define KS   68       // K chunk stride (4 mod 32 -> conflict-free for K pattern)
#define VS   72       // V chunk stride (8 mod 32 -> conflict-free for V pattern)
#define KVBUF 4608    // floats per double buffer (= 64*VS >= 64*KS)

__device__ __forceinline__ uint32_t f2tf32(float x) {
    uint32_t r;
    asm("cvt.rna.tf32.f32 %0, %1;" : "=r"(r) : "f"(x));
    return r;
}

__device__ __forceinline__ void mma_tf32(float c[4],
                                         uint32_t a0, uint32_t a1, uint32_t a2, uint32_t a3,
                                         uint32_t b0, uint32_t b1) {
    asm volatile(
        "mma.sync.aligned.m16n8k8.row.col.f32.tf32.tf32.f32 "
        "{%0,%1,%2,%3}, {%4,%5,%6,%7}, {%8,%9}, {%0,%1,%2,%3};\n"
        : "+f"(c[0]), "+f"(c[1]), "+f"(c[2]), "+f"(c[3])
        : "r"(a0), "r"(a1), "r"(a2), "r"(a3), "r"(b0), "r"(b1));
}

__device__ __forceinline__ void cp16(uint32_t dst, const float* src) {
    asm volatile("cp.async.cg.shared.global [%0], [%1], 16;\n" :: "r"(dst), "l"(src));
}
__device__ __forceinline__ void cp_commit() {
    asm volatile("cp.async.commit_group;\n" ::: "memory");
}
__device__ __forceinline__ void cp_wait_all() {
    asm volatile("cp.async.wait_group 0;\n" ::: "memory");
}

__global__ __launch_bounds__(512, 1)
void attn_mma3_kernel(const float* __restrict__ Q,
                      const float* __restrict__ K,
                      const float* __restrict__ V,
                      const float* __restrict__ bias,
                      float* __restrict__ out)
{
    extern __shared__ float sm[];
    float* sQhi = sm;                    // QT*QS
    float* sQlo = sQhi + QT * QS;        // QT*QS
    float* sP   = sQlo + QT * QS;        // QT*QS
    float* sRed = sP   + QT * QS;        // QT*8
    float* buf0 = sRed + QT * 8;         // KVBUF
    float* buf1 = buf0 + KVBUF;          // KVBUF

    const int t    = threadIdx.x;
    const int lane = t & 31;
    const int w    = t >> 5;
    const int qh   = w >> 3;            // 0..1 : q half (16 rows)
    const int cg   = w & 7;             // 0..7 : column group (n-tile within chunk)
    const int gid  = lane >> 2;
    const int tig  = lane & 3;
    const int rowA = qh * 16 + gid;

    const int bh = blockIdx.y;
    const int q0 = blockIdx.x * QT;

    const float* Qb = Q + ((size_t)bh * SQ + q0) * DD;
    const float* Kb = K + (size_t)bh * SQ * DD;
    const float* Vb = V + (size_t)bh * SQ * DD;
    float* outO = out + ((size_t)bh * SQ + q0) * DD;
    float* outA = out + (size_t)NBH * SQ * DD + ((size_t)bh * SQ + q0) * SQ;

    // ---- stage Q tile split hi/lo (512 threads cover 32x16 float4s exactly) ----
    {
        int r = t >> 4, c = t & 15;
        float4 q = ((const float4*)Qb)[r * 16 + c];
        float4 hi = make_float4(__uint_as_float(f2tf32(q.x)), __uint_as_float(f2tf32(q.y)),
                                __uint_as_float(f2tf32(q.z)), __uint_as_float(f2tf32(q.w)));
        float4 lo = make_float4(q.x - hi.x, q.y - hi.y, q.z - hi.z, q.w - hi.w);
        *(float4*)&sQhi[r * QS + c * 4] = hi;
        *(float4*)&sQlo[r * QS + c * 4] = lo;
    }

    float acc[16][4];
    #pragma unroll
    for (int j = 0; j < 16; j++) {
        acc[j][0] = 0.f; acc[j][1] = 0.f; acc[j][2] = 0.f; acc[j][3] = 0.f;
    }

    // ---- preload K chunk 0 into buf0 ----
    {
        uint32_t db = (uint32_t)__cvta_generic_to_shared(buf0);
        int r0 = t >> 4, c0 = t & 15;
        cp16(db + (uint32_t)((r0 * KS + c0 * 4) * 4), Kb + r0 * DD + c0 * 4);
        int i1 = t + 512; int r1 = i1 >> 4, c1 = i1 & 15;
        cp16(db + (uint32_t)((r1 * KS + c1 * 4) * 4), Kb + r1 * DD + c1 * 4);
        cp_commit();
    }

    // ================= phase 1: scores = Q K^T (3xTF32), double-buffered =================
    #pragma unroll
    for (int kt = 0; kt < 16; kt++) {
        cp_wait_all();
        __syncthreads();
        if (kt < 15) {
            uint32_t db = (uint32_t)__cvta_generic_to_shared((kt & 1) ? buf0 : buf1);
            const float* src = Kb + (size_t)(kt + 1) * 64 * DD;
            int r0 = t >> 4, c0 = t & 15;
            cp16(db + (uint32_t)((r0 * KS + c0 * 4) * 4), src + r0 * DD + c0 * 4);
            int i1 = t + 512; int r1 = i1 >> 4, c1 = i1 & 15;
            cp16(db + (uint32_t)((r1 * KS + c1 * 4) * 4), src + r1 * DD + c1 * 4);
            cp_commit();
        }
        const float* sK = (kt & 1) ? buf1 : buf0;

        #pragma unroll
        for (int ds = 0; ds < 8; ds++) {
            const int d0 = ds * 8;
            uint32_t aH0 = __float_as_uint(sQhi[rowA * QS + d0 + tig]);
            uint32_t aH1 = __float_as_uint(sQhi[(rowA + 8) * QS + d0 + tig]);
            uint32_t aH2 = __float_as_uint(sQhi[rowA * QS + d0 + tig + 4]);
            uint32_t aH3 = __float_as_uint(sQhi[(rowA + 8) * QS + d0 + tig + 4]);
            uint32_t aL0 = __float_as_uint(sQlo[rowA * QS + d0 + tig]);
            uint32_t aL1 = __float_as_uint(sQlo[(rowA + 8) * QS + d0 + tig]);
            uint32_t aL2 = __float_as_uint(sQlo[rowA * QS + d0 + tig + 4]);
            uint32_t aL3 = __float_as_uint(sQlo[(rowA + 8) * QS + d0 + tig + 4]);

            float k0 = sK[(cg * 8 + gid) * KS + d0 + tig];
            float k1 = sK[(cg * 8 + gid) * KS + d0 + tig + 4];
            uint32_t b0h = f2tf32(k0), b1h = f2tf32(k1);
            uint32_t b0l = __float_as_uint(k0 - __uint_as_float(b0h));
            uint32_t b1l = __float_as_uint(k1 - __uint_as_float(b1h));

            float* c = acc[kt];
            mma_tf32(c, aH0, aH1, aH2, aH3, b0h, b1h);
            mma_tf32(c, aH0, aH1, aH2, aH3, b0l, b1l);
            mma_tf32(c, aL0, aL1, aL2, aL3, b0h, b1h);
        }
    }

    // ================= phase 2: scale + bias + softmax, write attn from regs =================
    const float scale = 0.125f;
    float m1 = -1e30f, m2 = -1e30f;
    #pragma unroll
    for (int j = 0; j < 16; j++) {
        const int col = j * 64 + cg * 8 + 2 * tig;
        float2 b1v = *(const float2*)&bias[(size_t)(q0 + rowA) * SQ + col];
        float2 b2v = *(const float2*)&bias[(size_t)(q0 + rowA + 8) * SQ + col];
        acc[j][0] = acc[j][0] * scale + b1v.x;
        acc[j][1] = acc[j][1] * scale + b1v.y;
        acc[j][2] = acc[j][2] * scale + b2v.x;
        acc[j][3] = acc[j][3] * scale + b2v.y;
        m1 = fmaxf(m1, fmaxf(acc[j][0], acc[j][1]));
        m2 = fmaxf(m2, fmaxf(acc[j][2], acc[j][3]));
    }
    m1 = fmaxf(m1, __shfl_xor_sync(0xffffffffu, m1, 1));
    m1 = fmaxf(m1, __shfl_xor_sync(0xffffffffu, m1, 2));
    m2 = fmaxf(m2, __shfl_xor_sync(0xffffffffu, m2, 1));
    m2 = fmaxf(m2, __shfl_xor_sync(0xffffffffu, m2, 2));
    if (tig == 0) {
        sRed[rowA * 8 + cg]       = m1;
        sRed[(rowA + 8) * 8 + cg] = m2;
    }
    __syncthreads();
    m1 = -1e30f; m2 = -1e30f;
    #pragma unroll
    for (int i = 0; i < 8; i++) {
        m1 = fmaxf(m1, sRed[rowA * 8 + i]);
        m2 = fmaxf(m2, sRed[(rowA + 8) * 8 + i]);
    }

    float s1 = 0.f, s2 = 0.f;
    #pragma unroll
    for (int j = 0; j < 16; j++) {
        acc[j][0] = __expf(acc[j][0] - m1);
        acc[j][1] = __expf(acc[j][1] - m1);
        acc[j][2] = __expf(acc[j][2] - m2);
        acc[j][3] = __expf(acc[j][3] - m2);
        s1 += acc[j][0] + acc[j][1];
        s2 += acc[j][2] + acc[j][3];
    }
    s1 += __shfl_xor_sync(0xffffffffu, s1, 1);
    s1 += __shfl_xor_sync(0xffffffffu, s1, 2);
    s2 += __shfl_xor_sync(0xffffffffu, s2, 1);
    s2 += __shfl_xor_sync(0xffffffffu, s2, 2);
    __syncthreads();                       // everyone done reading maxes
    if (tig == 0) {
        sRed[rowA * 8 + cg]       = s1;
        sRed[(rowA + 8) * 8 + cg] = s2;
    }
    __syncthreads();
    s1 = 0.f; s2 = 0.f;
    #pragma unroll
    for (int i = 0; i < 8; i++) {
        s1 += sRed[rowA * 8 + i];
        s2 += sRed[(rowA + 8) * 8 + i];
    }
    const float inv1 = 1.0f / s1;
    const float inv2 = 1.0f / s2;

    #pragma unroll
    for (int j = 0; j < 16; j++) {
        acc[j][0] *= inv1; acc[j][1] *= inv1;
        acc[j][2] *= inv2; acc[j][3] *= inv2;
        const int col = j * 64 + cg * 8 + 2 * tig;
        *(float2*)&outA[(size_t)rowA * SQ + col]       = make_float2(acc[j][0], acc[j][1]);
        *(float2*)&outA[(size_t)(rowA + 8) * SQ + col] = make_float2(acc[j][2], acc[j][3]);
    }

    // ================= phase 3: out = P V (3xTF32), double-buffered V =================
    {   // preload V chunk 0 into buf0 (phase-1 use of buffers ended before phase-2 syncs)
        uint32_t db = (uint32_t)__cvta_generic_to_shared(buf0);
        int r0 = t >> 4, c0 = t & 15;
        cp16(db + (uint32_t)((r0 * VS + c0 * 4) * 4), Vb + r0 * DD + c0 * 4);
        int i1 = t + 512; int r1 = i1 >> 4, c1 = i1 & 15;
        cp16(db + (uint32_t)((r1 * VS + c1 * 4) * 4), Vb + r1 * DD + c1 * 4);
        cp_commit();
    }

    float o[4] = {0.f, 0.f, 0.f, 0.f};

    #pragma unroll
    for (int kt = 0; kt < 16; kt++) {
        cp_wait_all();
        __syncthreads();                  // V kt ready; prev-iter sP reads done
        // stage this warp's P tile of chunk kt
        *(float2*)&sP[rowA * QS + cg * 8 + 2 * tig]       = make_float2(acc[kt][0], acc[kt][1]);
        *(float2*)&sP[(rowA + 8) * QS + cg * 8 + 2 * tig] = make_float2(acc[kt][2], acc[kt][3]);
        if (kt < 15) {
            uint32_t db = (uint32_t)__cvta_generic_to_shared((kt & 1) ? buf0 : buf1);
            const float* src = Vb + (size_t)(kt + 1) * 64 * DD;
            int r0 = t >> 4, c0 = t & 15;
            cp16(db + (uint32_t)((r0 * VS + c0 * 4) * 4), src + r0 * DD + c0 * 4);
            int i1 = t + 512; int r1 = i1 >> 4, c1 = i1 & 15;
            cp16(db + (uint32_t)((r1 * VS + c1 * 4) * 4), src + r1 * DD + c1 * 4);
            cp_commit();
        }
        __syncthreads();                  // sP visible
        const float* sV = (kt & 1) ? buf1 : buf0;

        #pragma unroll
        for (int ks = 0; ks < 8; ks++) {
            const int k0 = ks * 8;
            float p0 = sP[rowA * QS + k0 + tig];
            float p1 = sP[(rowA + 8) * QS + k0 + tig];
            float p2 = sP[rowA * QS + k0 + tig + 4];
            float p3 = sP[(rowA + 8) * QS + k0 + tig + 4];
            uint32_t aH0 = f2tf32(p0), aH1 = f2tf32(p1), aH2 = f2tf32(p2), aH3 = f2tf32(p3);
            uint32_t aL0 = __float_as_uint(p0 - __uint_as_float(aH0));
            uint32_t aL1 = __float_as_uint(p1 - __uint_as_float(aH1));
            uint32_t aL2 = __float_as_uint(p2 - __uint_as_float(aH2));
            uint32_t aL3 = __float_as_uint(p3 - __uint_as_float(aH3));

            float v0 = sV[(k0 + tig) * VS + cg * 8 + gid];
            float v1 = sV[(k0 + tig + 4) * VS + cg * 8 + gid];
            uint32_t b0h = f2tf32(v0), b1h = f2tf32(v1);
            uint32_t b0l = __float_as_uint(v0 - __uint_as_float(b0h));
            uint32_t b1l = __float_as_uint(v1 - __uint_as_float(b1h));

            mma_tf32(o, aH0, aH1, aH2, aH3, b0h, b1h);
            mma_tf32(o, aH0, aH1, aH2, aH3, b0l, b1l);
            mma_tf32(o, aL0, aL1, aL2, aL3, b0h, b1h);
        }
    }

    // ---- write O ----
    {
        const int db = cg * 8 + 2 * tig;
        *(float2*)&outO[(size_t)rowA * DD + db]       = make_float2(o[0], o[1]);
        *(float2*)&outO[(size_t)(rowA + 8) * DD + db] = make_float2(o[2], o[3]);
    }
}

extern "C" void kernel_launch(void* const* d_in, const int* in_sizes, int n_in,
                              void* d_out, int out_size)
{
    const float* Q    = (const float*)d_in[0];
    const float* K    = (const float*)d_in[1];
    const float* V    = (const float*)d_in[2];
    const float* bias = (const float*)d_in[3];
    float* out        = (float*)d_out;

    const size_t smem_bytes = (size_t)(3 * QT * QS + QT * 8 + 2 * KVBUF) * sizeof(float);
    cudaFuncSetAttribute(attn_mma3_kernel,
                         cudaFuncAttributeMaxDynamicSharedMemorySize, (int)smem_bytes);

    dim3 grid(SQ / QT, NBH);
    attn_mma3_kernel<<<grid, 512, smem_bytes>>>(Q, K, V, bias, out);
}

// round 5
// speedup vs baseline: 4.3861x; 1.2559x over previous
#include <cuda_runtime.h>
#include <cstdint>

// B=4, H=16, S=1024, D=64 ; out = [O (64*1024*64 f32)] ++ [attn (64*1024*1024 f32)]
#define SQ 1024
#define DD 64
#define QT 32
#define NBH 64
#define QP 36     // u32 (bf16x2) row stride for packed planes: 32 pairs + pad (conflict-free)
#define OS 68     // O-reduction plane row stride (f32, 16B-aligned rows)

__device__ __forceinline__ uint32_t packbf(float lo, float hi) {
    uint32_t r;
    asm("cvt.rn.bf16x2.f32 %0, %1, %2;" : "=r"(r) : "f"(hi), "f"(lo));
    return r;
}
__device__ __forceinline__ float bf_lo(uint32_t p) { return __uint_as_float(p << 16); }
__device__ __forceinline__ float bf_hi(uint32_t p) { return __uint_as_float(p & 0xffff0000u); }

__device__ __forceinline__ void mma16(float* c, uint32_t a0, uint32_t a1, uint32_t a2, uint32_t a3,
                                      uint32_t b0, uint32_t b1) {
    asm volatile("mma.sync.aligned.m16n8k16.row.col.f32.bf16.bf16.f32 "
                 "{%0,%1,%2,%3}, {%4,%5,%6,%7}, {%8,%9}, {%0,%1,%2,%3};\n"
                 : "+f"(c[0]), "+f"(c[1]), "+f"(c[2]), "+f"(c[3])
                 : "r"(a0), "r"(a1), "r"(a2), "r"(a3), "r"(b0), "r"(b1));
}
__device__ __forceinline__ void mma8(float* c, uint32_t a0, uint32_t a1, uint32_t b0) {
    asm volatile("mma.sync.aligned.m16n8k8.row.col.f32.bf16.bf16.f32 "
                 "{%0,%1,%2,%3}, {%4,%5}, {%6}, {%0,%1,%2,%3};\n"
                 : "+f"(c[0]), "+f"(c[1]), "+f"(c[2]), "+f"(c[3])
                 : "r"(a0), "r"(a1), "r"(b0));
}

__global__ __launch_bounds__(512, 1)
void attn_bf16x3_kernel(const float* __restrict__ Q,
                        const float* __restrict__ K,
                        const float* __restrict__ V,
                        const float* __restrict__ bias,
                        float* __restrict__ out)
{
    extern __shared__ uint32_t smu[];
    uint32_t* sQh  = smu;                          // QT*QP
    uint32_t* sQl  = sQh + QT * QP;                // QT*QP
    float*    sRed = (float*)(sQl + QT * QP);      // QT*8
    uint32_t* sBuf = (uint32_t*)(sRed + QT * 8);   // 2 bufs x (hi+lo) x 64*QP
    float*    sOr  = (float*)(sBuf + 4 * 64 * QP); // 8 planes x 32*OS

    const int t    = threadIdx.x;
    const int lane = t & 31;
    const int w    = t >> 5;
    const int qh   = w >> 3;             // 0..1  (q half)
    const int cg   = w & 7;              // 0..7  (column group)
    const int gid  = lane >> 2;
    const int tig  = lane & 3;
    const int rowA = qh * 16 + gid;

    const int bh = blockIdx.y;
    const int q0 = blockIdx.x * QT;

    const float* Qb = Q + ((size_t)bh * SQ + q0) * DD;
    const float* Kb = K + (size_t)bh * SQ * DD;
    const float* Vb = V + (size_t)bh * SQ * DD;
    float* outO = out + ((size_t)bh * SQ + q0) * DD;
    float* outA = out + (size_t)NBH * SQ * DD + ((size_t)bh * SQ + q0) * SQ;

    // ---- stage Q: packed bf16 hi/lo planes (rows=q, pairs along d) ----
    {
        int r = t >> 4, c4 = t & 15;
        float4 q = ((const float4*)Qb)[r * 16 + c4];
        uint32_t h0 = packbf(q.x, q.y), h1 = packbf(q.z, q.w);
        uint32_t l0 = packbf(q.x - bf_lo(h0), q.y - bf_hi(h0));
        uint32_t l1 = packbf(q.z - bf_lo(h1), q.w - bf_hi(h1));
        *(uint2*)&sQh[r * QP + c4 * 2] = make_uint2(h0, h1);
        *(uint2*)&sQl[r * QP + c4 * 2] = make_uint2(l0, l1);
    }

    float acc[16][4];
    #pragma unroll
    for (int j = 0; j < 16; j++) {
        acc[j][0] = 0.f; acc[j][1] = 0.f; acc[j][2] = 0.f; acc[j][3] = 0.f;
    }

    // ================= phase 1: scores = Q K^T (3xBF16, k16 mma) =================
    // K chunk prefetch in registers; convert+STS at chunk top.
    const int kkey = t >> 3, kdqa = t & 7;                 // K staging mapping
    float4 ka = *(const float4*)(Kb + kkey * DD + kdqa * 4);
    float4 kb = *(const float4*)(Kb + kkey * DD + (kdqa + 8) * 4);

    #pragma unroll
    for (int kt = 0; kt < 16; kt++) {
        uint32_t* bh = sBuf + (kt & 1) * (2 * 64 * QP);
        uint32_t* bl = bh + 64 * QP;
        {
            uint32_t h0 = packbf(ka.x, ka.y), h1 = packbf(ka.z, ka.w);
            uint32_t l0 = packbf(ka.x - bf_lo(h0), ka.y - bf_hi(h0));
            uint32_t l1 = packbf(ka.z - bf_lo(h1), ka.w - bf_hi(h1));
            *(uint2*)&bh[kkey * QP + kdqa * 2] = make_uint2(h0, h1);
            *(uint2*)&bl[kkey * QP + kdqa * 2] = make_uint2(l0, l1);
            uint32_t h2 = packbf(kb.x, kb.y), h3 = packbf(kb.z, kb.w);
            uint32_t l2 = packbf(kb.x - bf_lo(h2), kb.y - bf_hi(h2));
            uint32_t l3 = packbf(kb.z - bf_lo(h3), kb.w - bf_hi(h3));
            *(uint2*)&bh[kkey * QP + (kdqa + 8) * 2] = make_uint2(h2, h3);
            *(uint2*)&bl[kkey * QP + (kdqa + 8) * 2] = make_uint2(l2, l3);
        }
        if (kt < 15) {    // prefetch next chunk (overlaps the barrier + mma below)
            const float* src = Kb + (size_t)(kt + 1) * 64 * DD;
            ka = *(const float4*)(src + kkey * DD + kdqa * 4);
            kb = *(const float4*)(src + kkey * DD + (kdqa + 8) * 4);
        }
        __syncthreads();

        #pragma unroll
        for (int ds = 0; ds < 4; ds++) {
            const int p0 = ds * 8 + tig;
            uint32_t aH0 = sQh[rowA * QP + p0];
            uint32_t aH1 = sQh[(rowA + 8) * QP + p0];
            uint32_t aH2 = sQh[rowA * QP + p0 + 4];
            uint32_t aH3 = sQh[(rowA + 8) * QP + p0 + 4];
            uint32_t aL0 = sQl[rowA * QP + p0];
            uint32_t aL1 = sQl[(rowA + 8) * QP + p0];
            uint32_t aL2 = sQl[rowA * QP + p0 + 4];
            uint32_t aL3 = sQl[(rowA + 8) * QP + p0 + 4];

            uint32_t bH0 = bh[(cg * 8 + gid) * QP + p0];
            uint32_t bH1 = bh[(cg * 8 + gid) * QP + p0 + 4];
            uint32_t bL0 = bl[(cg * 8 + gid) * QP + p0];
            uint32_t bL1 = bl[(cg * 8 + gid) * QP + p0 + 4];

            mma16(acc[kt], aH0, aH1, aH2, aH3, bH0, bH1);
            mma16(acc[kt], aH0, aH1, aH2, aH3, bL0, bL1);
            mma16(acc[kt], aL0, aL1, aL2, aL3, bH0, bH1);
        }
        __syncthreads();
    }

    // ================= phase 2: scale + bias + softmax, attn write from regs =================
    const float scale = 0.125f;
    float m1 = -1e30f, m2 = -1e30f;
    #pragma unroll
    for (int j = 0; j < 16; j++) {
        const int col = j * 64 + cg * 8 + 2 * tig;
        float2 b1v = *(const float2*)&bias[(size_t)(q0 + rowA) * SQ + col];
        float2 b2v = *(const float2*)&bias[(size_t)(q0 + rowA + 8) * SQ + col];
        acc[j][0] = acc[j][0] * scale + b1v.x;
        acc[j][1] = acc[j][1] * scale + b1v.y;
        acc[j][2] = acc[j][2] * scale + b2v.x;
        acc[j][3] = acc[j][3] * scale + b2v.y;
        m1 = fmaxf(m1, fmaxf(acc[j][0], acc[j][1]));
        m2 = fmaxf(m2, fmaxf(acc[j][2], acc[j][3]));
    }
    m1 = fmaxf(m1, __shfl_xor_sync(0xffffffffu, m1, 1));
    m1 = fmaxf(m1, __shfl_xor_sync(0xffffffffu, m1, 2));
    m2 = fmaxf(m2, __shfl_xor_sync(0xffffffffu, m2, 1));
    m2 = fmaxf(m2, __shfl_xor_sync(0xffffffffu, m2, 2));
    if (tig == 0) {
        sRed[rowA * 8 + cg]       = m1;
        sRed[(rowA + 8) * 8 + cg] = m2;
    }
    __syncthreads();
    m1 = -1e30f; m2 = -1e30f;
    #pragma unroll
    for (int i = 0; i < 8; i++) {
        m1 = fmaxf(m1, sRed[rowA * 8 + i]);
        m2 = fmaxf(m2, sRed[(rowA + 8) * 8 + i]);
    }
    float s1 = 0.f, s2 = 0.f;
    #pragma unroll
    for (int j = 0; j < 16; j++) {
        acc[j][0] = __expf(acc[j][0] - m1);
        acc[j][1] = __expf(acc[j][1] - m1);
        acc[j][2] = __expf(acc[j][2] - m2);
        acc[j][3] = __expf(acc[j][3] - m2);
        s1 += acc[j][0] + acc[j][1];
        s2 += acc[j][2] + acc[j][3];
    }
    s1 += __shfl_xor_sync(0xffffffffu, s1, 1);
    s1 += __shfl_xor_sync(0xffffffffu, s1, 2);
    s2 += __shfl_xor_sync(0xffffffffu, s2, 1);
    s2 += __shfl_xor_sync(0xffffffffu, s2, 2);
    __syncthreads();
    if (tig == 0) {
        sRed[rowA * 8 + cg]       = s1;
        sRed[(rowA + 8) * 8 + cg] = s2;
    }
    __syncthreads();
    s1 = 0.f; s2 = 0.f;
    #pragma unroll
    for (int i = 0; i < 8; i++) {
        s1 += sRed[rowA * 8 + i];
        s2 += sRed[(rowA + 8) * 8 + i];
    }
    const float inv1 = 1.0f / s1;
    const float inv2 = 1.0f / s2;
    #pragma unroll
    for (int j = 0; j < 16; j++) {
        acc[j][0] *= inv1; acc[j][1] *= inv1;
        acc[j][2] *= inv2; acc[j][3] *= inv2;
        const int col = j * 64 + cg * 8 + 2 * tig;
        *(float2*)&outA[(size_t)rowA * SQ + col]       = make_float2(acc[j][0], acc[j][1]);
        *(float2*)&outA[(size_t)(rowA + 8) * SQ + col] = make_float2(acc[j][2], acc[j][3]);
    }

    // ================= phase 3: O = P V (3xBF16 k8), P straight from acc =================
    float o[8][4];
    #pragma unroll
    for (int dt = 0; dt < 8; dt++) {
        o[dt][0] = 0.f; o[dt][1] = 0.f; o[dt][2] = 0.f; o[dt][3] = 0.f;
    }

    // V prefetch (transposed staging): thread -> (key pair kp, d quad dq4)
    const int kp = t & 31, dq4 = t >> 5;
    float4 v0 = *(const float4*)(Vb + (2 * kp) * DD + dq4 * 4);
    float4 v1 = *(const float4*)(Vb + (2 * kp + 1) * DD + dq4 * 4);

    #pragma unroll
    for (int kt = 0; kt < 16; kt++) {
        uint32_t* bh = sBuf + (kt & 1) * (2 * 64 * QP);
        uint32_t* bl = bh + 64 * QP;
        {   // transpose-convert: plane rows = d, pairs along key
            float vx0[4] = {v0.x, v0.y, v0.z, v0.w};
            float vx1[4] = {v1.x, v1.y, v1.z, v1.w};
            #pragma unroll
            for (int i = 0; i < 4; i++) {
                uint32_t h = packbf(vx0[i], vx1[i]);
                uint32_t l = packbf(vx0[i] - bf_lo(h), vx1[i] - bf_hi(h));
                bh[(dq4 * 4 + i) * QP + kp] = h;
                bl[(dq4 * 4 + i) * QP + kp] = l;
            }
        }
        if (kt < 15) {
            const float* src = Vb + (size_t)(kt + 1) * 64 * DD;
            v0 = *(const float4*)(src + (2 * kp) * DD + dq4 * 4);
            v1 = *(const float4*)(src + (2 * kp + 1) * DD + dq4 * 4);
        }
        __syncthreads();

        // A fragment directly from normalized acc (rows rowA/rowA+8, keys kt*64+cg*8..+7)
        uint32_t aH0 = packbf(acc[kt][0], acc[kt][1]);
        uint32_t aH1 = packbf(acc[kt][2], acc[kt][3]);
        uint32_t aL0 = packbf(acc[kt][0] - bf_lo(aH0), acc[kt][1] - bf_hi(aH0));
        uint32_t aL1 = packbf(acc[kt][2] - bf_lo(aH1), acc[kt][3] - bf_hi(aH1));

        #pragma unroll
        for (int dt = 0; dt < 8; dt++) {
            uint32_t bH = bh[(dt * 8 + gid) * QP + cg * 4 + tig];
            uint32_t bL = bl[(dt * 8 + gid) * QP + cg * 4 + tig];
            mma8(o[dt], aH0, aH1, bH);
            mma8(o[dt], aH0, aH1, bL);
            mma8(o[dt], aL0, aL1, bH);
        }
        __syncthreads();
    }

    // ---- cross-cg reduction of partial O, then coalesced store ----
    {
        float* myp = sOr + cg * (32 * OS);
        #pragma unroll
        for (int dt = 0; dt < 8; dt++) {
            *(float2*)&myp[rowA * OS + dt * 8 + 2 * tig]       = make_float2(o[dt][0], o[dt][1]);
            *(float2*)&myp[(rowA + 8) * OS + dt * 8 + 2 * tig] = make_float2(o[dt][2], o[dt][3]);
        }
    }
    __syncthreads();
    {
        int r = t >> 4, c4 = t & 15;
        float4 s = make_float4(0.f, 0.f, 0.f, 0.f);
        #pragma unroll
        for (int p = 0; p < 8; p++) {
            float4 v = *(float4*)&sOr[p * (32 * OS) + r * OS + c4 * 4];
            s.x += v.x; s.y += v.y; s.z += v.z; s.w += v.w;
        }
        *(float4*)&outO[(size_t)r * DD + c4 * 4] = s;
    }
}

extern "C" void kernel_launch(void* const* d_in, const int* in_sizes, int n_in,
                              void* d_out, int out_size)
{
    const float* Q    = (const float*)d_in[0];
    const float* K    = (const float*)d_in[1];
    const float* V    = (const float*)d_in[2];
    const float* bias = (const float*)d_in[3];
    float* out        = (float*)d_out;

    const size_t smem_bytes =
        (size_t)(2 * QT * QP + QT * 8 + 4 * 64 * QP + 8 * 32 * OS) * sizeof(uint32_t);
    cudaFuncSetAttribute(attn_bf16x3_kernel,
                         cudaFuncAttributeMaxDynamicSharedMemorySize, (int)smem_bytes);

    dim3 grid(SQ / QT, NBH);
    attn_bf16x3_kernel<<<grid, 512, smem_bytes>>>(Q, K, V, bias, out);
}

// round 6
// speedup vs baseline: 5.8548x; 1.3348x over previous
#include <cuda_runtime.h>
#include <cstdint>

// B=4, H=16, S=1024, D=64 ; out = [O (64*1024*64 f32)] ++ [attn (64*1024*1024 f32)]
#define SQ 1024
#define DD 64
#define QT 32
#define NBH 64
#define QP 36          // u32 (bf16x2) row stride for packed planes
#define VRS 68         // raw V row stride (floats) -> conflict-free frag reads
#define OS 68          // O-reduction plane row stride (f32)
#define KBUF (128*QP*2)   // u32 per K double-buffer half (hi+lo planes, 128 keys)
#define KHP  (128*QP)     // u32 offset of lo plane within a K buffer

__device__ __forceinline__ uint32_t packbf(float lo, float hi) {
    uint32_t r;
    asm("cvt.rn.bf16x2.f32 %0, %1, %2;" : "=r"(r) : "f"(hi), "f"(lo));
    return r;
}
__device__ __forceinline__ float bf_lo(uint32_t p) { return __uint_as_float(p << 16); }
__device__ __forceinline__ float bf_hi(uint32_t p) { return __uint_as_float(p & 0xffff0000u); }

__device__ __forceinline__ void mma16(float* c, uint32_t a0, uint32_t a1, uint32_t a2, uint32_t a3,
                                      uint32_t b0, uint32_t b1) {
    asm volatile("mma.sync.aligned.m16n8k16.row.col.f32.bf16.bf16.f32 "
                 "{%0,%1,%2,%3}, {%4,%5,%6,%7}, {%8,%9}, {%0,%1,%2,%3};\n"
                 : "+f"(c[0]), "+f"(c[1]), "+f"(c[2]), "+f"(c[3])
                 : "r"(a0), "r"(a1), "r"(a2), "r"(a3), "r"(b0), "r"(b1));
}
__device__ __forceinline__ void mma8(float* c, uint32_t a0, uint32_t a1, uint32_t b0) {
    asm volatile("mma.sync.aligned.m16n8k8.row.col.f32.bf16.bf16.f32 "
                 "{%0,%1,%2,%3}, {%4,%5}, {%6}, {%0,%1,%2,%3};\n"
                 : "+f"(c[0]), "+f"(c[1]), "+f"(c[2]), "+f"(c[3])
                 : "r"(a0), "r"(a1), "r"(b0));
}

__device__ __forceinline__ void cp16(uint32_t dst, const float* src) {
    asm volatile("cp.async.cg.shared.global [%0], [%1], 16;\n" :: "r"(dst), "l"(src));
}
__device__ __forceinline__ void cp_commit() {
    asm volatile("cp.async.commit_group;\n" ::: "memory");
}
template <int N>
__device__ __forceinline__ void cp_wait() {
    asm volatile("cp.async.wait_group %0;\n" :: "n"(N) : "memory");
}

__global__ __launch_bounds__(512, 1)
void attn_bf16x3_j2_kernel(const float* __restrict__ Q,
                           const float* __restrict__ K,
                           const float* __restrict__ V,
                           const float* __restrict__ bias,
                           float* __restrict__ out)
{
    extern __shared__ uint32_t smu[];
    uint32_t* sQh  = smu;                          // 32*QP
    uint32_t* sQl  = sQh + QT * QP;                // 32*QP
    float*    sRed = (float*)(sQl + QT * QP);      // 32*8
    uint32_t* slab = (uint32_t*)(sRed + QT * 8);   // 2 * KBUF (K planes / raw V)
    float*    sOr  = (float*)(slab + 2 * KBUF);    // 8 * 32 * OS

    const int t    = threadIdx.x;
    const int lane = t & 31;
    const int w    = t >> 5;
    const int qh   = w >> 3;             // 0..1 (q half)
    const int cg   = w & 7;              // 0..7 (column group)
    const int gid  = lane >> 2;
    const int tig  = lane & 3;
    const int rowA = qh * 16 + gid;

    const int bh = blockIdx.y;
    const int q0 = blockIdx.x * QT;

    const float* Qb = Q + ((size_t)bh * SQ + q0) * DD;
    const float* Kb = K + (size_t)bh * SQ * DD;
    const float* Vb = V + (size_t)bh * SQ * DD;
    float* outO = out + ((size_t)bh * SQ + q0) * DD;
    float* outA = out + (size_t)NBH * SQ * DD + ((size_t)bh * SQ + q0) * SQ;

    // ---- stage Q: packed bf16 hi/lo planes ----
    {
        int r = t >> 4, c4 = t & 15;
        float4 q = ((const float4*)Qb)[r * 16 + c4];
        uint32_t h0 = packbf(q.x, q.y), h1 = packbf(q.z, q.w);
        uint32_t l0 = packbf(q.x - bf_lo(h0), q.y - bf_hi(h0));
        uint32_t l1 = packbf(q.z - bf_lo(h1), q.w - bf_hi(h1));
        *(uint2*)&sQh[r * QP + c4 * 2] = make_uint2(h0, h1);
        *(uint2*)&sQl[r * QP + c4 * 2] = make_uint2(l0, l1);
    }

    float acc[16][4];
    #pragma unroll
    for (int j = 0; j < 16; j++) {
        acc[j][0] = 0.f; acc[j][1] = 0.f; acc[j][2] = 0.f; acc[j][3] = 0.f;
    }

    // ================= phase 1: scores = Q K^T (3xBF16 k16), 128-key chunks, J=2 =================
    const int kkey = t >> 3, kdqa = t & 7;
    float4 ka, kb;

    // load one 64-key sub-chunk into (ka, kb)
    #define LDK(chunk64) do {                                              \
        const float* _s = Kb + (size_t)(chunk64) * 64 * DD;                \
        ka = *(const float4*)(_s + kkey * DD + kdqa * 4);                  \
        kb = *(const float4*)(_s + kkey * DD + (kdqa + 8) * 4);            \
    } while (0)

    // convert regs -> planes of buffer, sub row block
    #define STK(bufp, sub) do {                                            \
        uint32_t* _h = (bufp);                                             \
        uint32_t* _l = (bufp) + KHP;                                       \
        int _r = (sub) * 64 + kkey;                                        \
        uint32_t h0 = packbf(ka.x, ka.y), h1 = packbf(ka.z, ka.w);         \
        uint32_t l0 = packbf(ka.x - bf_lo(h0), ka.y - bf_hi(h0));          \
        uint32_t l1 = packbf(ka.z - bf_lo(h1), ka.w - bf_hi(h1));          \
        *(uint2*)&_h[_r * QP + kdqa * 2] = make_uint2(h0, h1);             \
        *(uint2*)&_l[_r * QP + kdqa * 2] = make_uint2(l0, l1);             \
        uint32_t h2 = packbf(kb.x, kb.y), h3 = packbf(kb.z, kb.w);         \
        uint32_t l2 = packbf(kb.x - bf_lo(h2), kb.y - bf_hi(h2));          \
        uint32_t l3 = packbf(kb.z - bf_lo(h3), kb.w - bf_hi(h3));         \
        *(uint2*)&_h[_r * QP + (kdqa + 8) * 2] = make_uint2(h2, h3);       \
        *(uint2*)&_l[_r * QP + (kdqa + 8) * 2] = make_uint2(l2, l3);       \
    } while (0)

    // prologue: stage chunk0 (subs 0,1); preload (chunk1, sub0)
    LDK(0); STK(slab, 0);
    LDK(1); STK(slab, 1);
    LDK(2);
    __syncthreads();

    #pragma unroll
    for (int c = 0; c < 8; c++) {
        uint32_t* bp = slab + (c & 1) * KBUF;
        uint32_t* bq = slab + ((c + 1) & 1) * KBUF;
        if (c < 7) { STK(bq, 0); LDK(2 * c + 3); }

        #pragma unroll
        for (int ds = 0; ds < 4; ds++) {
            const int p0 = ds * 8 + tig;
            uint32_t aH0 = sQh[rowA * QP + p0];
            uint32_t aH1 = sQh[(rowA + 8) * QP + p0];
            uint32_t aH2 = sQh[rowA * QP + p0 + 4];
            uint32_t aH3 = sQh[(rowA + 8) * QP + p0 + 4];
            uint32_t aL0 = sQl[rowA * QP + p0];
            uint32_t aL1 = sQl[(rowA + 8) * QP + p0];
            uint32_t aL2 = sQl[rowA * QP + p0 + 4];
            uint32_t aL3 = sQl[(rowA + 8) * QP + p0 + 4];

            #pragma unroll
            for (int sub = 0; sub < 2; sub++) {
                const int row = sub * 64 + cg * 8 + gid;
                uint32_t bH0 = bp[row * QP + p0];
                uint32_t bH1 = bp[row * QP + p0 + 4];
                uint32_t bL0 = bp[KHP + row * QP + p0];
                uint32_t bL1 = bp[KHP + row * QP + p0 + 4];
                float* cc = acc[c * 2 + sub];
                mma16(cc, aH0, aH1, aH2, aH3, bH0, bH1);
                mma16(cc, aH0, aH1, aH2, aH3, bL0, bL1);
                mma16(cc, aL0, aL1, aL2, aL3, bH0, bH1);
            }
        }
        if (c < 7) { STK(bq, 1); if (c < 6) LDK(2 * c + 4); }
        __syncthreads();
    }

    // ---- kick off V chunk 0 (raw f32, cp.async) into slab buffer 0 — overlaps softmax ----
    float* vb0 = (float*)slab;
    float* vb1 = (float*)(slab + KBUF);
    {
        uint32_t dst = (uint32_t)__cvta_generic_to_shared(vb0);
        #pragma unroll
        for (int n = 0; n < 4; n++) {
            int i = t + n * 512; int key = i >> 4, c16 = i & 15;
            cp16(dst + (uint32_t)(key * VRS + c16 * 4) * 4, Vb + key * DD + c16 * 4);
        }
        cp_commit();
    }

    // ================= phase 2: scale + bias + softmax, attn write from regs =================
    const float scale = 0.125f;
    float m1 = -1e30f, m2 = -1e30f;
    #pragma unroll
    for (int j = 0; j < 16; j++) {
        const int col = j * 64 + cg * 8 + 2 * tig;
        float2 b1v = *(const float2*)&bias[(size_t)(q0 + rowA) * SQ + col];
        float2 b2v = *(const float2*)&bias[(size_t)(q0 + rowA + 8) * SQ + col];
        acc[j][0] = acc[j][0] * scale + b1v.x;
        acc[j][1] = acc[j][1] * scale + b1v.y;
        acc[j][2] = acc[j][2] * scale + b2v.x;
        acc[j][3] = acc[j][3] * scale + b2v.y;
        m1 = fmaxf(m1, fmaxf(acc[j][0], acc[j][1]));
        m2 = fmaxf(m2, fmaxf(acc[j][2], acc[j][3]));
    }
    m1 = fmaxf(m1, __shfl_xor_sync(0xffffffffu, m1, 1));
    m1 = fmaxf(m1, __shfl_xor_sync(0xffffffffu, m1, 2));
    m2 = fmaxf(m2, __shfl_xor_sync(0xffffffffu, m2, 1));
    m2 = fmaxf(m2, __shfl_xor_sync(0xffffffffu, m2, 2));
    if (tig == 0) {
        sRed[rowA * 8 + cg]       = m1;
        sRed[(rowA + 8) * 8 + cg] = m2;
    }
    __syncthreads();
    m1 = -1e30f; m2 = -1e30f;
    #pragma unroll
    for (int i = 0; i < 8; i++) {
        m1 = fmaxf(m1, sRed[rowA * 8 + i]);
        m2 = fmaxf(m2, sRed[(rowA + 8) * 8 + i]);
    }
    float s1 = 0.f, s2 = 0.f;
    #pragma unroll
    for (int j = 0; j < 16; j++) {
        acc[j][0] = __expf(acc[j][0] - m1);
        acc[j][1] = __expf(acc[j][1] - m1);
        acc[j][2] = __expf(acc[j][2] - m2);
        acc[j][3] = __expf(acc[j][3] - m2);
        s1 += acc[j][0] + acc[j][1];
        s2 += acc[j][2] + acc[j][3];
    }
    s1 += __shfl_xor_sync(0xffffffffu, s1, 1);
    s1 += __shfl_xor_sync(0xffffffffu, s1, 2);
    s2 += __shfl_xor_sync(0xffffffffu, s2, 1);
    s2 += __shfl_xor_sync(0xffffffffu, s2, 2);
    __syncthreads();
    if (tig == 0) {
        sRed[rowA * 8 + cg]       = s1;
        sRed[(rowA + 8) * 8 + cg] = s2;
    }
    __syncthreads();
    s1 = 0.f; s2 = 0.f;
    #pragma unroll
    for (int i = 0; i < 8; i++) {
        s1 += sRed[rowA * 8 + i];
        s2 += sRed[(rowA + 8) * 8 + i];
    }
    const float inv1 = 1.0f / s1;
    const float inv2 = 1.0f / s2;
    #pragma unroll
    for (int j = 0; j < 16; j++) {
        acc[j][0] *= inv1; acc[j][1] *= inv1;
        acc[j][2] *= inv2; acc[j][3] *= inv2;
        const int col = j * 64 + cg * 8 + 2 * tig;
        *(float2*)&outA[(size_t)rowA * SQ + col]       = make_float2(acc[j][0], acc[j][1]);
        *(float2*)&outA[(size_t)(rowA + 8) * SQ + col] = make_float2(acc[j][2], acc[j][3]);
    }

    // ================= phase 3: O = P V (3xBF16 k8), raw-V cp.async, inline convert =================
    float o[8][4];
    #pragma unroll
    for (int dt = 0; dt < 8; dt++) {
        o[dt][0] = 0.f; o[dt][1] = 0.f; o[dt][2] = 0.f; o[dt][3] = 0.f;
    }

    #pragma unroll
    for (int c = 0; c < 8; c++) {
        if (c > 0) __syncthreads();           // prior readers of target buffer done
        if (c < 7) {
            float* nb = ((c + 1) & 1) ? vb1 : vb0;
            uint32_t dst = (uint32_t)__cvta_generic_to_shared(nb);
            const float* src = Vb + (size_t)(c + 1) * 128 * DD;
            #pragma unroll
            for (int n = 0; n < 4; n++) {
                int i = t + n * 512; int key = i >> 4, c16 = i & 15;
                cp16(dst + (uint32_t)(key * VRS + c16 * 4) * 4, src + key * DD + c16 * 4);
            }
            cp_commit();
            cp_wait<1>();
        } else {
            cp_wait<0>();
        }
        __syncthreads();                      // chunk c visible to all
        const float* vb = (c & 1) ? vb1 : vb0;

        #pragma unroll
        for (int sub = 0; sub < 2; sub++) {
            const int kt = c * 2 + sub;
            uint32_t aH0 = packbf(acc[kt][0], acc[kt][1]);
            uint32_t aH1 = packbf(acc[kt][2], acc[kt][3]);
            uint32_t aL0 = packbf(acc[kt][0] - bf_lo(aH0), acc[kt][1] - bf_hi(aH0));
            uint32_t aL1 = packbf(acc[kt][2] - bf_lo(aH1), acc[kt][3] - bf_hi(aH1));
            const float* r0 = vb + (size_t)(sub * 64 + cg * 8 + 2 * tig) * VRS;
            const float* r1 = r0 + VRS;
            #pragma unroll
            for (int dt = 0; dt < 8; dt++) {
                float va = r0[dt * 8 + gid];
                float vx = r1[dt * 8 + gid];
                uint32_t bH = packbf(va, vx);
                uint32_t bL = packbf(va - bf_lo(bH), vx - bf_hi(bH));
                mma8(o[dt], aH0, aH1, bH);
                mma8(o[dt], aH0, aH1, bL);
                mma8(o[dt], aL0, aL1, bH);
            }
        }
    }

    // ---- cross-cg reduction of partial O, then coalesced store ----
    __syncthreads();
    {
        float* myp = sOr + cg * (32 * OS);
        #pragma unroll
        for (int dt = 0; dt < 8; dt++) {
            *(float2*)&myp[rowA * OS + dt * 8 + 2 * tig]       = make_float2(o[dt][0], o[dt][1]);
            *(float2*)&myp[(rowA + 8) * OS + dt * 8 + 2 * tig] = make_float2(o[dt][2], o[dt][3]);
        }
    }
    __syncthreads();
    {
        int r = t >> 4, c4 = t & 15;
        float4 s = make_float4(0.f, 0.f, 0.f, 0.f);
        #pragma unroll
        for (int p = 0; p < 8; p++) {
            float4 v = *(float4*)&sOr[p * (32 * OS) + r * OS + c4 * 4];
            s.x += v.x; s.y += v.y; s.z += v.z; s.w += v.w;
        }
        *(float4*)&outO[(size_t)r * DD + c4 * 4] = s;
    }
}

extern "C" void kernel_launch(void* const* d_in, const int* in_sizes, int n_in,
                              void* d_out, int out_size)
{
    const float* Q    = (const float*)d_in[0];
    const float* K    = (const float*)d_in[1];
    const float* V    = (const float*)d_in[2];
    const float* bias = (const float*)d_in[3];
    float* out        = (float*)d_out;

    const size_t smem_u32 = (size_t)(2 * QT * QP) + QT * 8 + 2 * KBUF + 8 * 32 * OS;
    const size_t smem_bytes = smem_u32 * sizeof(uint32_t);
    cudaFuncSetAttribute(attn_bf16x3_j2_kernel,
                         cudaFuncAttributeMaxDynamicSharedMemorySize, (int)smem_bytes);

    dim3 grid(SQ / QT, NBH);
    attn_bf16x3_j2_kernel<<<grid, 512, smem_bytes>>>(Q, K, V, bias, out);
}